// round 10
// baseline (speedup 1.0000x reference)
#include <cuda_runtime.h>
#include <cuda_bf16.h>
#include <math.h>
#include <stdint.h>

#define MAXT 4096
#define D_BB 768
#define KPAD 960          // 160 feat(+pad) + 768 bb + 32 pad
#define CH   64           // k per chunk
#define NCH  15           // chunks
#define NSTG 4            // smem pipeline stages
#define BUFB 24576        // per stage: Ah 4K | Al 4K | Bh 8K | Bl 8K
#define SMEM_TOTAL (NSTG * BUFB)

typedef unsigned long long u64;
typedef unsigned int       u32;

__device__ __align__(16) __nv_bfloat16 g_Bh[128 * KPAD];
__device__ __align__(16) __nv_bfloat16 g_Bl[128 * KPAD];
__device__ float4 g_dots[2 * MAXT];        // per-half partial (p3,p4,p5,p6)
__device__ int    g_cnt[128];              // per-tile arrival counters

// ---- helpers -----------------------------------------------------------------
__device__ __forceinline__ u32 smem_u32(const void* p) {
    u32 a;
    asm("{ .reg .u64 t; cvta.to.shared.u64 t, %1; cvt.u32.u64 %0, t; }"
        : "=r"(a) : "l"(p));
    return a;
}
__device__ __forceinline__ u32 SWZ(u32 b) { return b ^ ((b >> 3) & 0x70); }

__device__ __forceinline__ u32 pack_bf2(float lo, float hi) {
    __nv_bfloat162 v = __floats2bfloat162_rn(lo, hi);
    return *(u32*)&v;
}
__device__ __forceinline__ float bfr(float x) {
    return __bfloat162float(__float2bfloat16_rn(x));
}

#define LDMX4(r, addr) \
    asm volatile("ldmatrix.sync.aligned.m8n8.x4.shared.b16 {%0,%1,%2,%3}, [%4];" \
        : "=r"((r)[0]), "=r"((r)[1]), "=r"((r)[2]), "=r"((r)[3]) : "r"(addr))

#define MMA16816(d, a, b0, b1) \
    asm volatile("mma.sync.aligned.m16n8k16.row.col.f32.bf16.bf16.f32 " \
        "{%0,%1,%2,%3}, {%4,%5,%6,%7}, {%8,%9}, {%0,%1,%2,%3};" \
        : "+f"((d)[0]), "+f"((d)[1]), "+f"((d)[2]), "+f"((d)[3]) \
        : "r"((a)[0]), "r"((a)[1]), "r"((a)[2]), "r"((a)[3]), "r"(b0), "r"(b1))

#define CPA16(dst, src) \
    asm volatile("cp.async.cg.shared.global [%0], [%1], 16;" \
        :: "r"(dst), "l"(src) : "memory")
#define CPA_COMMIT() asm volatile("cp.async.commit_group;" ::: "memory")
#define CPA_WAIT(n)  asm volatile("cp.async.wait_group %0;" :: "n"(n) : "memory")

#define STS128(r0, r1, r2, r3, sa) \
    asm volatile("st.shared.v4.b32 [%0], {%1, %2, %3, %4};" \
        :: "r"(sa), "r"(r0), "r"(r1), "r"(r2), "r"(r3) : "memory")

// -----------------------------------------------------------------------------
// Prep: W1 [918,128] fp32 -> g_Bh/g_Bl [128 n][960 k] bf16 split (row remap).
// -----------------------------------------------------------------------------
__global__ void prep_B(const float* __restrict__ W1) {
    int id = blockIdx.x * 256 + threadIdx.x;        // 128 n * 240 groups of 4
    if (id >= 128 * 240) return;
    int n  = id / 240;
    int k4 = (id % 240) * 4;
    u32 hw[2], lw[2];
    #pragma unroll
    for (int p = 0; p < 2; p++) {
        float v0 = 0.f, v1 = 0.f;
        int g0 = k4 + p * 2, g1 = g0 + 1;
        if (g0 < 150)                    v0 = W1[(size_t)g0 * 128 + n];
        else if (g0 >= 160 && g0 < 928)  v0 = W1[(size_t)(g0 - 10) * 128 + n];
        if (g1 < 150)                    v1 = W1[(size_t)g1 * 128 + n];
        else if (g1 >= 160 && g1 < 928)  v1 = W1[(size_t)(g1 - 10) * 128 + n];
        float h0 = bfr(v0), h1 = bfr(v1);
        hw[p] = pack_bf2(v0, v1);
        lw[p] = pack_bf2(v0 - h0, v1 - h1);
    }
    *(u64*)&g_Bh[(size_t)n * KPAD + k4] = (u64)hw[0] | ((u64)hw[1] << 32);
    *(u64*)&g_Bl[(size_t)n * KPAD + k4] = (u64)lw[0] | ((u64)lw[1] << 32);
}

// -----------------------------------------------------------------------------
// GEMM: grid (T/32 tiles, 2 N-halves). 256 threads (8 warps: 2M x 4N).
// Each CTA: h[32 tasks x 64 cols] complete over K -> local relu + partial dots.
// 4 floats/task exchanged via g_dots; last-arriving CTA combines.
// -----------------------------------------------------------------------------
__global__ void __launch_bounds__(256, 2)
critic_mma(const float* __restrict__ bb,
           const float* __restrict__ res,   const float* __restrict__ fr,
           const float* __restrict__ estep, const float* __restrict__ enode,
           const float* __restrict__ ccl,   const float* __restrict__ cnd,
           const float* __restrict__ b1,
           const float* __restrict__ W3, const float* __restrict__ b3,
           const float* __restrict__ W4, const float* __restrict__ b4,
           const float* __restrict__ W5, const float* __restrict__ b5,
           const float* __restrict__ W6, const float* __restrict__ b6,
           float* __restrict__ out, int T)
{
    extern __shared__ __align__(16) char dsm[];
    __shared__ int winflag;
    const u32 sb = smem_u32(dsm);

    const int tid  = threadIdx.x;
    const int lane = tid & 31;
    const int wid  = tid >> 5;
    const int mtile = blockIdx.x;
    const int nh    = blockIdx.y;          // N-half: cols [nh*64, nh*64+64)
    const int mbase = mtile * 32;

    const int m0w = (wid & 1) * 16;
    const int n0w = (wid >> 1) * 16;       // local col base 0..48

    // ---- A loader mapping: thread -> (row, 8 consecutive k) ----
    const int ar = tid >> 3;                // 0..31
    const int ak = (tid & 7) * 8;           // 0..56
    int atask = mbase + ar; if (atask >= T) atask = T - 1;
    const float* bbrow = bb + (size_t)atask * D_BB;
    const u32 aoff = SWZ((u32)(ar * 128 + ak * 2));

    // ---- B loader mapping: 2 x (local row, 16B seg) per thread ----
    int brow[2], bseg[2]; u32 bdst[2];
    #pragma unroll
    for (int i = 0; i < 2; i++) {
        int id = tid + i * 256;              // 0..511 -> 64 rows x 8 segs
        brow[i] = id >> 3;
        bseg[i] = id & 7;
        bdst[i] = SWZ((u32)(brow[i] * 128 + bseg[i] * 16));
    }

    // ---- fragment address bases ----
    const u32 aRowByte = (u32)((m0w + (lane & 7) + ((lane >> 3) & 1) * 8) * 128
                               + (lane >> 4) * 16);
    const u32 bRowByte = (u32)((n0w + (lane >> 4) * 8 + (lane & 7)) * 128
                               + ((lane >> 3) & 1) * 16);

    float Da[2][4], Db[2][4], Dc[2][4];
    #pragma unroll
    for (int h = 0; h < 2; h++)
        #pragma unroll
        for (int j = 0; j < 4; j++) { Da[h][j] = 0.f; Db[h][j] = 0.f; Dc[h][j] = 0.f; }

    auto loadA_gen = [&](int c, float* x) {
        int g0 = c * CH + ak;
        if (g0 >= 160 && g0 + 8 <= 928) {
            const float4* p = (const float4*)(bbrow + (g0 - 160));
            float4 v0 = p[0], v1 = p[1];
            x[0]=v0.x; x[1]=v0.y; x[2]=v0.z; x[3]=v0.w;
            x[4]=v1.x; x[5]=v1.y; x[6]=v1.z; x[7]=v1.w;
        } else {
            #pragma unroll
            for (int j = 0; j < 8; j++) {
                int gk = g0 + j;
                float v = 0.f;
                if (gk < 150) {
                    int nn = gk / 30, rem = gk - nn * 30;
                    int mm = rem / 6, oo = rem - mm * 6;
                    v = res[atask * 5 + nn] * fr[atask * 5 + mm] * estep[atask * 6 + oo];
                } else if (gk >= 160 && gk < 928) {
                    v = bbrow[gk - 160];
                }
                x[j] = v;
            }
        }
    };
    auto loadA_bb = [&](int c, float* x) {
        int g0 = c * CH + ak;
        if (g0 + 8 <= 928) {
            const float4* p = (const float4*)(bbrow + (g0 - 160));
            float4 v0 = p[0], v1 = p[1];
            x[0]=v0.x; x[1]=v0.y; x[2]=v0.z; x[3]=v0.w;
            x[4]=v1.x; x[5]=v1.y; x[6]=v1.z; x[7]=v1.w;
        } else {
            #pragma unroll
            for (int j = 0; j < 8; j++) x[j] = 0.f;
        }
    };
    auto storeA = [&](int c, const float* x) {
        const u32 base = sb + (u32)(c % NSTG) * BUFB;
        u32 hw[4], lw[4];
        #pragma unroll
        for (int q = 0; q < 4; q++) {
            float x0 = x[2*q], x1 = x[2*q+1];
            float h0 = bfr(x0), h1 = bfr(x1);
            hw[q] = pack_bf2(x0, x1);
            lw[q] = pack_bf2(x0 - h0, x1 - h1);
        }
        STS128(hw[0], hw[1], hw[2], hw[3], base + aoff);
        STS128(lw[0], lw[1], lw[2], lw[3], base + 4096 + aoff);
    };
    auto issueB = [&](int c) {
        const u32 base = sb + (u32)(c % NSTG) * BUFB;
        #pragma unroll
        for (int i = 0; i < 2; i++) {
            const size_t so = (size_t)(nh * 64 + brow[i]) * KPAD + c * CH + bseg[i] * 8;
            CPA16(base + 8192  + bdst[i], g_Bh + so);
            CPA16(base + 16384 + bdst[i], g_Bl + so);
        }
    };

    // fragment double buffers
    u32 fa_h[2][4], fa_l[2][4], fb_h[2][4], fb_l[2][4];
    auto loadFrag = [&](int c, int ks, int buf) {
        const u32 base = sb + (u32)(c % NSTG) * BUFB;
        const u32 ao = SWZ(aRowByte + ks * 32);
        const u32 bo = SWZ(bRowByte + ks * 32);
        LDMX4(fa_h[buf], base + ao);
        LDMX4(fb_h[buf], base + 8192 + bo);
        LDMX4(fa_l[buf], base + 4096 + ao);
        LDMX4(fb_l[buf], base + 16384 + bo);
    };
    auto mmas = [&](int buf) {
        MMA16816(Da[0], fa_h[buf], fb_h[buf][0], fb_h[buf][1]);
        MMA16816(Da[1], fa_h[buf], fb_h[buf][2], fb_h[buf][3]);
        MMA16816(Db[0], fa_h[buf], fb_l[buf][0], fb_l[buf][1]);
        MMA16816(Db[1], fa_h[buf], fb_l[buf][2], fb_l[buf][3]);
        MMA16816(Dc[0], fa_l[buf], fb_h[buf][0], fb_h[buf][1]);
        MMA16816(Dc[1], fa_l[buf], fb_h[buf][2], fb_h[buf][3]);
    };
    auto compute = [&](int c) {
        loadFrag(c, 0, 0);
        loadFrag(c, 1, 1);
        mmas(0);
        loadFrag(c, 2, 0);
        mmas(1);
        loadFrag(c, 3, 1);
        mmas(0);
        mmas(1);
    };

    // ---- prologue: fill stages 0..2, prefetch A(3) into regs ----
    {
        float x0[8], x1[8], x2[8];
        loadA_gen(0, x0); loadA_gen(1, x1); loadA_gen(2, x2);
        storeA(0, x0); issueB(0); CPA_COMMIT();
        storeA(1, x1); issueB(1); CPA_COMMIT();
        storeA(2, x2); issueB(2); CPA_COMMIT();
    }
    float xcur[8];
    loadA_bb(3, xcur);
    CPA_WAIT(2);
    __syncthreads();

    // ---- main loop ----
    for (int c = 0; c < NCH; c++) {
        compute(c);
        if (c + 3 < NCH) {
            storeA(c + 3, xcur);
            if (c + 4 < NCH) loadA_bb(c + 4, xcur);
            issueB(c + 3); CPA_COMMIT();
            CPA_WAIT(2);
        } else if (c + 2 < NCH) {
            CPA_WAIT(1);
        } else if (c + 1 < NCH) {
            CPA_WAIT(0);
        }
        __syncthreads();
    }

    // ---- stage D to smem: [32 tasks][68] local cols ----
    float* hsm = (float*)dsm;
    const int drow = m0w + (lane >> 2);
    #pragma unroll
    for (int h = 0; h < 2; h++) {
        int col = n0w + h * 8 + 2 * (lane & 3);
        float d0 = Da[h][0] + Db[h][0] + Dc[h][0];
        float d1 = Da[h][1] + Db[h][1] + Dc[h][1];
        float d2 = Da[h][2] + Db[h][2] + Dc[h][2];
        float d3 = Da[h][3] + Db[h][3] + Dc[h][3];
        *(float2*)&hsm[drow * 68 + col]       = make_float2(d0, d1);
        *(float2*)&hsm[(drow + 8) * 68 + col] = make_float2(d2, d3);
    }
    __syncthreads();

    // ---- local relu + partial dots over 64 cols: 8 warps x 4 tasks ----
    {
        const int c0 = lane * 2;            // 2 local cols per lane
        const int gc = nh * 64 + c0;
        float2 bj = *(const float2*)&b1[gc];
        float2 w3 = *(const float2*)&W3[gc];
        float2 w4 = *(const float2*)&W4[gc];
        float2 w5 = *(const float2*)&W5[gc];
        float2 w6 = *(const float2*)&W6[gc];
        #pragma unroll
        for (int it = 0; it < 4; it++) {
            int m = wid * 4 + it;
            float2 s = *(const float2*)&hsm[m * 68 + c0];
            float h0 = fmaxf(s.x + bj.x, 0.f);
            float h1 = fmaxf(s.y + bj.y, 0.f);
            float p3 = h0 * w3.x + h1 * w3.y;
            float p4 = h0 * w4.x + h1 * w4.y;
            float p5 = h0 * w5.x + h1 * w5.y;
            float p6 = h0 * w6.x + h1 * w6.y;
            #pragma unroll
            for (int off = 16; off; off >>= 1) {
                p3 += __shfl_xor_sync(0xffffffffu, p3, off);
                p4 += __shfl_xor_sync(0xffffffffu, p4, off);
                p5 += __shfl_xor_sync(0xffffffffu, p5, off);
                p6 += __shfl_xor_sync(0xffffffffu, p6, off);
            }
            int task = mbase + m;
            if (lane == 0 && task < T)
                g_dots[(size_t)nh * MAXT + task] = make_float4(p3, p4, p5, p6);
        }
    }
    __threadfence();
    __syncthreads();
    if (tid == 0) {
        int old = atomicAdd(&g_cnt[mtile], 1);
        winflag = old & 1;
    }
    __syncthreads();
    if (!winflag) return;
    __threadfence();

    // ---- final combine (last CTA): 8 warps x 4 tasks ----
    const float B3 = b3[0], B4 = b4[0], B5 = b5[0], B6 = b6[0];
    #pragma unroll
    for (int it = 0; it < 4; it++) {
        int m = wid * 4 + it;
        int task = mbase + m;
        bool ok = (task < T);
        int rt = ok ? task : (T - 1);

        float4 d0 = g_dots[rt];
        float4 d1 = g_dots[(size_t)MAXT + rt];
        float p3 = d0.x + d1.x, p4 = d0.y + d1.y;
        float p5 = d0.z + d1.z, p6 = d0.w + d1.w;

        float se = enode[(size_t)rt * 64 + lane] + enode[(size_t)rt * 64 + lane + 32];
        float sc = (lane < 4) ? ccl[rt * 4 + lane] : 0.0f;
        float sn = cnd[(size_t)rt * 32 + lane];
        #pragma unroll
        for (int off = 16; off; off >>= 1) {
            se += __shfl_xor_sync(0xffffffffu, se, off);
            sc += __shfl_xor_sync(0xffffffffu, sc, off);
            sn += __shfl_xor_sync(0xffffffffu, sn, off);
        }
        if (lane == 0 && ok) {
            float me = se * (1.0f / 64.0f);
            float ss = sc * sn;
            float y51 = 1.0f / (1.0f + expf(-(p3 * me + B3)));
            float y61 = p4 * me + B4;
            float y52 = 1.0f / (1.0f + expf(-(p5 * ss + B5)));
            float y62 = p6 * ss + B6;
            float p = y51 * y52;
            out[task] = (1.0f - p) * (-100.0f) + p * (y61 + y62);
        }
    }
}

// -----------------------------------------------------------------------------
extern "C" void kernel_launch(void* const* d_in, const int* in_sizes, int n_in,
                              void* d_out, int out_size) {
    const float* bb    = (const float*)d_in[2];
    const float* res   = (const float*)d_in[3];
    const float* fr    = (const float*)d_in[4];
    const float* estep = (const float*)d_in[5];
    const float* enode = (const float*)d_in[6];
    const float* ccl   = (const float*)d_in[7];
    const float* cnd   = (const float*)d_in[8];
    const float* W1    = (const float*)d_in[9];
    const float* b1    = (const float*)d_in[10];
    const float* W3    = (const float*)d_in[11];
    const float* b3    = (const float*)d_in[12];
    const float* W4    = (const float*)d_in[13];
    const float* b4    = (const float*)d_in[14];
    const float* W5    = (const float*)d_in[15];
    const float* b5    = (const float*)d_in[16];
    const float* W6    = (const float*)d_in[17];
    const float* b6    = (const float*)d_in[18];

    int T = in_sizes[2] / D_BB;
    if (T > MAXT) T = MAXT;

    static int cfg = 0;
    if (!cfg) {
        cudaFuncSetAttribute(critic_mma,
                             cudaFuncAttributeMaxDynamicSharedMemorySize,
                             SMEM_TOTAL);
        cfg = 1;
    }

    prep_B<<<120, 256>>>(W1);
    dim3 grid((T + 31) / 32, 2);
    critic_mma<<<grid, 256, SMEM_TOTAL>>>(
        bb, res, fr, estep, enode, ccl, cnd,
        b1, W3, b3, W4, b4, W5, b5, W6, b6, (float*)d_out, T);
}

// round 11
// speedup vs baseline: 1.6605x; 1.6605x over previous
#include <cuda_runtime.h>
#include <cuda_fp16.h>
#include <math.h>
#include <stdint.h>

#define D_BB 768
#define KPAD 960          // 160 feat(+pad) + 768 bb + 32 pad
#define CH   64           // k per chunk
#define NCH  15           // chunks
#define NSTG 4            // smem pipeline stages
#define BUFB 24576        // per stage: Ah 4K | Al 4K | B 16K
#define HSM_BYTES (4 * 32 * 132 * 4)       // 67584: kg-partial D slabs
#define SMEM_TOTAL (NSTG * BUFB)           // 98304 > HSM_BYTES

typedef unsigned long long u64;
typedef unsigned int       u32;

// ---- W1 as fp16, transposed [n][k], remapped/padded -------------------------
__device__ __align__(16) __half g_B[128 * KPAD];

// ---- helpers -----------------------------------------------------------------
__device__ __forceinline__ u32 smem_u32(const void* p) {
    u32 a;
    asm("{ .reg .u64 t; cvta.to.shared.u64 t, %1; cvt.u32.u64 %0, t; }"
        : "=r"(a) : "l"(p));
    return a;
}
__device__ __forceinline__ u32 SWZ(u32 b) { return b ^ ((b >> 3) & 0x70); }

__device__ __forceinline__ u32 pack_h2(float lo, float hi) {
    __half2 v = __floats2half2_rn(lo, hi);
    return *(u32*)&v;
}

#define LDMX4(r, addr) \
    asm volatile("ldmatrix.sync.aligned.m8n8.x4.shared.b16 {%0,%1,%2,%3}, [%4];" \
        : "=r"((r)[0]), "=r"((r)[1]), "=r"((r)[2]), "=r"((r)[3]) : "r"(addr))

#define MMAF16(d, a, b0, b1) \
    asm volatile("mma.sync.aligned.m16n8k16.row.col.f32.f16.f16.f32 " \
        "{%0,%1,%2,%3}, {%4,%5,%6,%7}, {%8,%9}, {%0,%1,%2,%3};" \
        : "+f"((d)[0]), "+f"((d)[1]), "+f"((d)[2]), "+f"((d)[3]) \
        : "r"((a)[0]), "r"((a)[1]), "r"((a)[2]), "r"((a)[3]), "r"(b0), "r"(b1))

#define CPA16(dst, src) \
    asm volatile("cp.async.cg.shared.global [%0], [%1], 16;" \
        :: "r"(dst), "l"(src) : "memory")
#define CPA_COMMIT() asm volatile("cp.async.commit_group;" ::: "memory")
#define CPA_WAIT(n)  asm volatile("cp.async.wait_group %0;" :: "n"(n) : "memory")

#define STS64(r0, r1, sa) \
    asm volatile("st.shared.v2.b32 [%0], {%1, %2};" \
        :: "r"(sa), "r"(r0), "r"(r1) : "memory")

// -----------------------------------------------------------------------------
// Prep: W1 [918,128] fp32 -> g_B [128 n][960 k] fp16 (row remap + zero pad).
// -----------------------------------------------------------------------------
__global__ void prep_B(const float* __restrict__ W1) {
    int id = blockIdx.x * 256 + threadIdx.x;        // 128 n * 240 groups of 4
    if (id >= 128 * 240) return;
    int n  = id / 240;
    int k4 = (id % 240) * 4;
    u32 w[2];
    #pragma unroll
    for (int p = 0; p < 2; p++) {
        float v0 = 0.f, v1 = 0.f;
        int g0 = k4 + p * 2, g1 = g0 + 1;
        if (g0 < 150)                    v0 = W1[(size_t)g0 * 128 + n];
        else if (g0 >= 160 && g0 < 928)  v0 = W1[(size_t)(g0 - 10) * 128 + n];
        if (g1 < 150)                    v1 = W1[(size_t)g1 * 128 + n];
        else if (g1 >= 160 && g1 < 928)  v1 = W1[(size_t)(g1 - 10) * 128 + n];
        w[p] = pack_h2(v0, v1);
    }
    *(u64*)&g_B[(size_t)n * KPAD + k4] = (u64)w[0] | ((u64)w[1] << 32);
}

// -----------------------------------------------------------------------------
// Fused kernel: grid = T/32 CTAs, 512 threads.
// 16 warps = 2M x 2N x 4K-groups; warp tile 16 rows x 64 cols, one kstep/chunk.
// 2-pass fp16 split-precision (A = Ah + Al fp16, B fp16).
// Cross-kg reduction + full epilogue in-CTA.
// -----------------------------------------------------------------------------
__global__ void __launch_bounds__(512)
critic_mma(const float* __restrict__ bb,
           const float* __restrict__ res,   const float* __restrict__ fr,
           const float* __restrict__ estep, const float* __restrict__ enode,
           const float* __restrict__ ccl,   const float* __restrict__ cnd,
           const float* __restrict__ b1,
           const float* __restrict__ W3, const float* __restrict__ b3,
           const float* __restrict__ W4, const float* __restrict__ b4,
           const float* __restrict__ W5, const float* __restrict__ b5,
           const float* __restrict__ W6, const float* __restrict__ b6,
           float* __restrict__ out, int T)
{
    extern __shared__ __align__(16) char dsm[];
    const u32 sb = smem_u32(dsm);

    const int tid  = threadIdx.x;
    const int lane = tid & 31;
    const int wid  = tid >> 5;
    const int mbase = blockIdx.x * 32;

    // warp decomposition: kg = k-quarter, mg = M-half, ng = N-half
    const int kg = wid & 3;
    const int mg = (wid >> 2) & 1;
    const int ng = wid >> 3;

    // ---- A loader mapping: thread -> (row, 4 consecutive k) ----
    const int ar = tid >> 4;                // 0..31
    const int ak = (tid & 15) * 4;          // 0..60
    int atask = mbase + ar; if (atask >= T) atask = T - 1;
    const float* bbrow = bb + (size_t)atask * D_BB;
    const u32 aoff = SWZ((u32)(ar * 128 + ak * 2));

    // ---- B loader mapping: 2 x (row, 16B seg) per thread ----
    int brow[2], bseg[2]; u32 bdst[2];
    #pragma unroll
    for (int i = 0; i < 2; i++) {
        int id = tid + i * 512;              // 1024 = 128 rows x 8 segs
        brow[i] = id >> 3;
        bseg[i] = id & 7;
        bdst[i] = SWZ((u32)(brow[i] * 128 + bseg[i] * 16));
    }

    // ---- fragment offsets (within stage), swizzled once ----
    const u32 aOff = SWZ((u32)((mg * 16 + (lane & 7) + ((lane >> 3) & 1) * 8) * 128
                               + (lane >> 4) * 16 + kg * 32));
    u32 bOff[4];
    #pragma unroll
    for (int j = 0; j < 4; j++)
        bOff[j] = SWZ((u32)((ng * 64 + j * 16 + (lane >> 4) * 8 + (lane & 7)) * 128
                            + ((lane >> 3) & 1) * 16 + kg * 32));

    // accumulators: 8 n8-frags x 2 passes
    float Da[8][4], Db[8][4];
    #pragma unroll
    for (int j = 0; j < 8; j++)
        #pragma unroll
        for (int q = 0; q < 4; q++) { Da[j][q] = 0.f; Db[j][q] = 0.f; }

    auto loadA_gen = [&](int c, float* x) {
        int g0 = c * CH + ak;
        if (g0 >= 160 && g0 + 4 <= 928) {
            float4 v = *(const float4*)(bbrow + (g0 - 160));
            x[0] = v.x; x[1] = v.y; x[2] = v.z; x[3] = v.w;
        } else {
            #pragma unroll
            for (int j = 0; j < 4; j++) {
                int gk = g0 + j;
                float v = 0.f;
                if (gk < 150) {
                    int nn = gk / 30, rem = gk - nn * 30;
                    int mm = rem / 6, oo = rem - mm * 6;
                    v = res[atask * 5 + nn] * fr[atask * 5 + mm] * estep[atask * 6 + oo];
                } else if (gk >= 160 && gk < 928) {
                    v = bbrow[gk - 160];
                }
                x[j] = v;
            }
        }
    };
    auto loadA_bb = [&](int c, float* x) {
        int g0 = c * CH + ak;
        if (g0 + 4 <= 928) {
            float4 v = *(const float4*)(bbrow + (g0 - 160));
            x[0] = v.x; x[1] = v.y; x[2] = v.z; x[3] = v.w;
        } else {
            x[0] = x[1] = x[2] = x[3] = 0.f;
        }
    };
    auto storeA = [&](int c, const float* x) {
        const u32 base = sb + (u32)(c % NSTG) * BUFB;
        float h0 = __half2float(__float2half_rn(x[0]));
        float h1 = __half2float(__float2half_rn(x[1]));
        float h2 = __half2float(__float2half_rn(x[2]));
        float h3 = __half2float(__float2half_rn(x[3]));
        STS64(pack_h2(x[0], x[1]), pack_h2(x[2], x[3]), base + aoff);
        STS64(pack_h2(x[0] - h0, x[1] - h1), pack_h2(x[2] - h2, x[3] - h3),
              base + 4096 + aoff);
    };
    auto issueB = [&](int c) {
        const u32 base = sb + (u32)(c % NSTG) * BUFB;
        #pragma unroll
        for (int i = 0; i < 2; i++) {
            const size_t so = (size_t)brow[i] * KPAD + c * CH + bseg[i] * 8;
            CPA16(base + 8192 + bdst[i], g_B + so);
        }
    };
    auto compute = [&](int c) {
        const u32 base = sb + (u32)(c % NSTG) * BUFB;
        u32 ah[4], al[4], bf[4][4];
        LDMX4(ah, base + aOff);
        LDMX4(al, base + 4096 + aOff);
        #pragma unroll
        for (int j = 0; j < 4; j++) LDMX4(bf[j], base + 8192 + bOff[j]);
        #pragma unroll
        for (int j = 0; j < 4; j++) {
            MMAF16(Da[2*j],   ah, bf[j][0], bf[j][1]);
            MMAF16(Da[2*j+1], ah, bf[j][2], bf[j][3]);
        }
        #pragma unroll
        for (int j = 0; j < 4; j++) {
            MMAF16(Db[2*j],   al, bf[j][0], bf[j][1]);
            MMAF16(Db[2*j+1], al, bf[j][2], bf[j][3]);
        }
    };

    // ---- prologue: fill stages 0..2, prefetch A(3) into regs ----
    {
        float x0[4], x1[4], x2[4];
        loadA_gen(0, x0); loadA_gen(1, x1); loadA_gen(2, x2);
        storeA(0, x0); issueB(0); CPA_COMMIT();
        storeA(1, x1); issueB(1); CPA_COMMIT();
        storeA(2, x2); issueB(2); CPA_COMMIT();
    }
    float xcur[4];
    loadA_bb(3, xcur);
    CPA_WAIT(2);
    __syncthreads();

    // ---- main loop: 1 sync/chunk ----
    for (int c = 0; c < NCH; c++) {
        compute(c);
        if (c + 3 < NCH) {
            storeA(c + 3, xcur);
            if (c + 4 < NCH) loadA_bb(c + 4, xcur);
            issueB(c + 3); CPA_COMMIT();
            CPA_WAIT(2);
        } else if (c + 2 < NCH) {
            CPA_WAIT(1);
        } else if (c + 1 < NCH) {
            CPA_WAIT(0);
        }
        __syncthreads();
    }

    // ---- write kg-partial D to smem: hsm[4][32][132] ----
    float* hsm = (float*)dsm;
    {
        float* slab = hsm + kg * (32 * 132);
        const int r0 = mg * 16 + (lane >> 2);
        #pragma unroll
        for (int j = 0; j < 4; j++) {
            #pragma unroll
            for (int h2 = 0; h2 < 2; h2++) {
                int jj = 2 * j + h2;
                int col = ng * 64 + j * 16 + h2 * 8 + 2 * (lane & 3);
                float d0 = Da[jj][0] + Db[jj][0];
                float d1 = Da[jj][1] + Db[jj][1];
                float d2 = Da[jj][2] + Db[jj][2];
                float d3 = Da[jj][3] + Db[jj][3];
                *(float2*)&slab[r0 * 132 + col]       = make_float2(d0, d1);
                *(float2*)&slab[(r0 + 8) * 132 + col] = make_float2(d2, d3);
            }
        }
    }
    __syncthreads();

    // ---- epilogue: 16 warps x 2 tasks; reduce 4 kg slabs inline ----
    const int n0 = lane * 4;
    const float4 bj = *(const float4*)&b1[n0];
    const float4 w3 = *(const float4*)&W3[n0];
    const float4 w4 = *(const float4*)&W4[n0];
    const float4 w5 = *(const float4*)&W5[n0];
    const float4 w6 = *(const float4*)&W6[n0];
    const float B3 = b3[0], B4 = b4[0], B5 = b5[0], B6 = b6[0];

    #pragma unroll
    for (int it = 0; it < 2; it++) {
        int m = wid * 2 + it;
        int task = mbase + m;
        bool ok = (task < T);
        int rt = ok ? task : (T - 1);

        float4 s = *(const float4*)&hsm[m * 132 + n0];
        #pragma unroll
        for (int q = 1; q < 4; q++) {
            float4 p = *(const float4*)&hsm[q * (32 * 132) + m * 132 + n0];
            s.x += p.x; s.y += p.y; s.z += p.z; s.w += p.w;
        }
        float h0 = fmaxf(s.x + bj.x, 0.f), h1 = fmaxf(s.y + bj.y, 0.f);
        float h2 = fmaxf(s.z + bj.z, 0.f), h3 = fmaxf(s.w + bj.w, 0.f);
        float p3 = h0*w3.x + h1*w3.y + h2*w3.z + h3*w3.w;
        float p4 = h0*w4.x + h1*w4.y + h2*w4.z + h3*w4.w;
        float p5 = h0*w5.x + h1*w5.y + h2*w5.z + h3*w5.w;
        float p6 = h0*w6.x + h1*w6.y + h2*w6.z + h3*w6.w;

        float se = enode[(size_t)rt * 64 + lane] + enode[(size_t)rt * 64 + lane + 32];
        float sc = (lane < 4) ? ccl[rt * 4 + lane] : 0.0f;
        float sn = cnd[(size_t)rt * 32 + lane];

        #pragma unroll
        for (int off = 16; off; off >>= 1) {
            p3 += __shfl_xor_sync(0xffffffffu, p3, off);
            p4 += __shfl_xor_sync(0xffffffffu, p4, off);
            p5 += __shfl_xor_sync(0xffffffffu, p5, off);
            p6 += __shfl_xor_sync(0xffffffffu, p6, off);
            se += __shfl_xor_sync(0xffffffffu, se, off);
            sc += __shfl_xor_sync(0xffffffffu, sc, off);
            sn += __shfl_xor_sync(0xffffffffu, sn, off);
        }
        if (lane == 0 && ok) {
            float me = se * (1.0f / 64.0f);
            float ss = sc * sn;
            float y51 = 1.0f / (1.0f + expf(-(p3 * me + B3)));
            float y61 = p4 * me + B4;
            float y52 = 1.0f / (1.0f + expf(-(p5 * ss + B5)));
            float y62 = p6 * ss + B6;
            float p = y51 * y52;
            out[task] = (1.0f - p) * (-100.0f) + p * (y61 + y62);
        }
    }
}

// -----------------------------------------------------------------------------
extern "C" void kernel_launch(void* const* d_in, const int* in_sizes, int n_in,
                              void* d_out, int out_size) {
    const float* bb    = (const float*)d_in[2];
    const float* res   = (const float*)d_in[3];
    const float* fr    = (const float*)d_in[4];
    const float* estep = (const float*)d_in[5];
    const float* enode = (const float*)d_in[6];
    const float* ccl   = (const float*)d_in[7];
    const float* cnd   = (const float*)d_in[8];
    const float* W1    = (const float*)d_in[9];
    const float* b1    = (const float*)d_in[10];
    const float* W3    = (const float*)d_in[11];
    const float* b3    = (const float*)d_in[12];
    const float* W4    = (const float*)d_in[13];
    const float* b4    = (const float*)d_in[14];
    const float* W5    = (const float*)d_in[15];
    const float* b5    = (const float*)d_in[16];
    const float* W6    = (const float*)d_in[17];
    const float* b6    = (const float*)d_in[18];

    int T = in_sizes[2] / D_BB;

    static int cfg = 0;
    if (!cfg) {
        cudaFuncSetAttribute(critic_mma,
                             cudaFuncAttributeMaxDynamicSharedMemorySize,
                             SMEM_TOTAL);
        cfg = 1;
    }

    prep_B<<<120, 256>>>(W1);
    critic_mma<<<(T + 31) / 32, 512, SMEM_TOTAL>>>(
        bb, res, fr, estep, enode, ccl, cnd,
        b1, W3, b3, W4, b4, W5, b5, W6, b6, (float*)d_out, T);
}

// round 12
// speedup vs baseline: 1.6890x; 1.0172x over previous
#include <cuda_runtime.h>
#include <cuda_fp16.h>
#include <math.h>
#include <stdint.h>

#define D_BB 768
#define KPAD 960          // 160 feat(+pad) + 768 bb + 32 pad
#define CH   64           // k per sub-chunk
#define NCH  15           // sub-chunks
#define NPAIR 8           // chunk pairs (last pair = chunk 14 only)
#define SUBB 24576        // per sub-stage: Ah 4K | Al 4K | B 16K
#define SMEM_TOTAL (6 * SUBB)   // 3 pair-stages x 2 sub-stages = 147456

typedef unsigned long long u64;
typedef unsigned int       u32;

// ---- W1 as fp16, transposed [n][k], remapped/padded -------------------------
__device__ __align__(16) __half g_B[128 * KPAD];

// ---- helpers -----------------------------------------------------------------
__device__ __forceinline__ u32 smem_u32(const void* p) {
    u32 a;
    asm("{ .reg .u64 t; cvta.to.shared.u64 t, %1; cvt.u32.u64 %0, t; }"
        : "=r"(a) : "l"(p));
    return a;
}
__device__ __forceinline__ u32 SWZ(u32 b) { return b ^ ((b >> 3) & 0x70); }

__device__ __forceinline__ u32 pack_h2(float lo, float hi) {
    __half2 v = __floats2half2_rn(lo, hi);
    return *(u32*)&v;
}

#define LDMX4(r, addr) \
    asm volatile("ldmatrix.sync.aligned.m8n8.x4.shared.b16 {%0,%1,%2,%3}, [%4];" \
        : "=r"((r)[0]), "=r"((r)[1]), "=r"((r)[2]), "=r"((r)[3]) : "r"(addr))

#define MMAF16(d, a, b0, b1) \
    asm volatile("mma.sync.aligned.m16n8k16.row.col.f32.f16.f16.f32 " \
        "{%0,%1,%2,%3}, {%4,%5,%6,%7}, {%8,%9}, {%0,%1,%2,%3};" \
        : "+f"((d)[0]), "+f"((d)[1]), "+f"((d)[2]), "+f"((d)[3]) \
        : "r"((a)[0]), "r"((a)[1]), "r"((a)[2]), "r"((a)[3]), "r"(b0), "r"(b1))

#define CPA16(dst, src) \
    asm volatile("cp.async.cg.shared.global [%0], [%1], 16;" \
        :: "r"(dst), "l"(src) : "memory")
#define CPA_COMMIT() asm volatile("cp.async.commit_group;" ::: "memory")
#define CPA_WAIT(n)  asm volatile("cp.async.wait_group %0;" :: "n"(n) : "memory")

#define STS64(r0, r1, sa) \
    asm volatile("st.shared.v2.b32 [%0], {%1, %2};" \
        :: "r"(sa), "r"(r0), "r"(r1) : "memory")

// -----------------------------------------------------------------------------
// Prep: W1 [918,128] fp32 -> g_B [128 n][960 k] fp16 (row remap + zero pad).
// -----------------------------------------------------------------------------
__global__ void prep_B(const float* __restrict__ W1) {
    int id = blockIdx.x * 256 + threadIdx.x;        // 128 n * 240 groups of 4
    if (id >= 128 * 240) return;
    int n  = id / 240;
    int k4 = (id % 240) * 4;
    u32 w[2];
    #pragma unroll
    for (int p = 0; p < 2; p++) {
        float v0 = 0.f, v1 = 0.f;
        int g0 = k4 + p * 2, g1 = g0 + 1;
        if (g0 < 150)                    v0 = W1[(size_t)g0 * 128 + n];
        else if (g0 >= 160 && g0 < 928)  v0 = W1[(size_t)(g0 - 10) * 128 + n];
        if (g1 < 150)                    v1 = W1[(size_t)g1 * 128 + n];
        else if (g1 >= 160 && g1 < 928)  v1 = W1[(size_t)(g1 - 10) * 128 + n];
        w[p] = pack_h2(v0, v1);
    }
    *(u64*)&g_B[(size_t)n * KPAD + k4] = (u64)w[0] | ((u64)w[1] << 32);
}

// -----------------------------------------------------------------------------
// Fused kernel: grid = T/32 CTAs, 512 threads.
// 16 warps = 2M x 2N x 4K-groups; warp tile 16 rows x 64 cols.
// Paired-chunk pipeline: 3 pair-stages, ONE sync per 2 chunks.
// 2-pass fp16 split-precision (A = Ah + Al fp16, B fp16).
// -----------------------------------------------------------------------------
__global__ void __launch_bounds__(512)
critic_mma(const float* __restrict__ bb,
           const float* __restrict__ res,   const float* __restrict__ fr,
           const float* __restrict__ estep, const float* __restrict__ enode,
           const float* __restrict__ ccl,   const float* __restrict__ cnd,
           const float* __restrict__ b1,
           const float* __restrict__ W3, const float* __restrict__ b3,
           const float* __restrict__ W4, const float* __restrict__ b4,
           const float* __restrict__ W5, const float* __restrict__ b5,
           const float* __restrict__ W6, const float* __restrict__ b6,
           float* __restrict__ out, int T)
{
    extern __shared__ __align__(16) char dsm[];
    const u32 sb = smem_u32(dsm);

    const int tid  = threadIdx.x;
    const int lane = tid & 31;
    const int wid  = tid >> 5;
    const int mbase = blockIdx.x * 32;

    const int kg = wid & 3;
    const int mg = (wid >> 2) & 1;
    const int ng = wid >> 3;

    // sub-stage base for chunk c: pair (c>>1)%3, half c&1
    auto stageBase = [&](int c) -> u32 {
        return sb + (u32)((((c >> 1) % 3) * 2 + (c & 1)) * SUBB);
    };

    // ---- A loader mapping: thread -> (row, 4 consecutive k) ----
    const int ar = tid >> 4;
    const int ak = (tid & 15) * 4;
    int atask = mbase + ar; if (atask >= T) atask = T - 1;
    const float* bbrow = bb + (size_t)atask * D_BB;
    const u32 aoff = SWZ((u32)(ar * 128 + ak * 2));

    // ---- B loader mapping: 2 x (row, 16B seg) per thread ----
    int brow[2], bseg[2]; u32 bdst[2];
    #pragma unroll
    for (int i = 0; i < 2; i++) {
        int id = tid + i * 512;
        brow[i] = id >> 3;
        bseg[i] = id & 7;
        bdst[i] = SWZ((u32)(brow[i] * 128 + bseg[i] * 16));
    }

    // ---- fragment offsets (within sub-stage) ----
    const u32 aOff = SWZ((u32)((mg * 16 + (lane & 7) + ((lane >> 3) & 1) * 8) * 128
                               + (lane >> 4) * 16 + kg * 32));
    u32 bOff[4];
    #pragma unroll
    for (int j = 0; j < 4; j++)
        bOff[j] = SWZ((u32)((ng * 64 + j * 16 + (lane >> 4) * 8 + (lane & 7)) * 128
                            + ((lane >> 3) & 1) * 16 + kg * 32));

    float Da[8][4], Db[8][4];
    #pragma unroll
    for (int j = 0; j < 8; j++)
        #pragma unroll
        for (int q = 0; q < 4; q++) { Da[j][q] = 0.f; Db[j][q] = 0.f; }

    auto loadA_gen = [&](int c, float* x) {
        int g0 = c * CH + ak;
        if (g0 >= 160 && g0 + 4 <= 928) {
            float4 v = *(const float4*)(bbrow + (g0 - 160));
            x[0] = v.x; x[1] = v.y; x[2] = v.z; x[3] = v.w;
        } else {
            #pragma unroll
            for (int j = 0; j < 4; j++) {
                int gk = g0 + j;
                float v = 0.f;
                if (gk < 150) {
                    int nn = gk / 30, rem = gk - nn * 30;
                    int mm = rem / 6, oo = rem - mm * 6;
                    v = res[atask * 5 + nn] * fr[atask * 5 + mm] * estep[atask * 6 + oo];
                } else if (gk >= 160 && gk < 928) {
                    v = bbrow[gk - 160];
                }
                x[j] = v;
            }
        }
    };
    auto loadA_bb = [&](int c, float* x) {
        int g0 = c * CH + ak;
        if (g0 + 4 <= 928) {
            float4 v = *(const float4*)(bbrow + (g0 - 160));
            x[0] = v.x; x[1] = v.y; x[2] = v.z; x[3] = v.w;
        } else {
            x[0] = x[1] = x[2] = x[3] = 0.f;
        }
    };
    auto storeA = [&](int c, const float* x) {
        const u32 base = stageBase(c);
        float h0 = __half2float(__float2half_rn(x[0]));
        float h1 = __half2float(__float2half_rn(x[1]));
        float h2 = __half2float(__float2half_rn(x[2]));
        float h3 = __half2float(__float2half_rn(x[3]));
        STS64(pack_h2(x[0], x[1]), pack_h2(x[2], x[3]), base + aoff);
        STS64(pack_h2(x[0] - h0, x[1] - h1), pack_h2(x[2] - h2, x[3] - h3),
              base + 4096 + aoff);
    };
    auto issueB = [&](int c) {
        const u32 base = stageBase(c);
        #pragma unroll
        for (int i = 0; i < 2; i++) {
            const size_t so = (size_t)brow[i] * KPAD + c * CH + bseg[i] * 8;
            CPA16(base + 8192 + bdst[i], g_B + so);
        }
    };
    auto compute = [&](int c) {
        const u32 base = stageBase(c);
        u32 ah[4], al[4], bf[4][4];
        LDMX4(ah, base + aOff);
        LDMX4(al, base + 4096 + aOff);
        #pragma unroll
        for (int j = 0; j < 4; j++) LDMX4(bf[j], base + 8192 + bOff[j]);
        #pragma unroll
        for (int j = 0; j < 4; j++) {
            MMAF16(Da[2*j],   ah, bf[j][0], bf[j][1]);
            MMAF16(Da[2*j+1], ah, bf[j][2], bf[j][3]);
        }
        #pragma unroll
        for (int j = 0; j < 4; j++) {
            MMAF16(Db[2*j],   al, bf[j][0], bf[j][1]);
            MMAF16(Db[2*j+1], al, bf[j][2], bf[j][3]);
        }
    };

    // ---- prologue: pairs 0,1 staged; A for pair 2 prefetched ----
    float xa[4], xb[4];
    loadA_gen(0, xa); loadA_gen(1, xb);
    storeA(0, xa); storeA(1, xb); issueB(0); issueB(1); CPA_COMMIT();
    loadA_gen(2, xa); loadA_gen(3, xb);
    storeA(2, xa); storeA(3, xb); issueB(2); issueB(3); CPA_COMMIT();
    loadA_bb(4, xa); loadA_bb(5, xb);
    CPA_WAIT(1);             // pair 0 arrived
    __syncthreads();

    // ---- main loop: one sync per pair ----
    for (int p = 0; p < NPAIR; p++) {
        const int c0 = 2 * p;
        compute(c0);
        if (c0 + 1 < NCH) compute(c0 + 1);

        if (p + 2 < NPAIR) {
            const int cA = c0 + 4, cB = c0 + 5;
            storeA(cA, xa);
            if (cB < NCH) storeA(cB, xb);
            if (p + 3 < NPAIR) {
                loadA_bb(cA + 2, xa);
                if (cB + 2 < NCH) loadA_bb(cB + 2, xb);
            }
            issueB(cA);
            if (cB < NCH) issueB(cB);
            CPA_COMMIT();
            CPA_WAIT(1);     // pair p+1 arrived
        } else if (p + 1 < NPAIR) {
            CPA_WAIT(0);     // final pair arrived
        }
        __syncthreads();
    }

    // ---- write kg-partial D to smem: hsm[4][32][132] ----
    float* hsm = (float*)dsm;
    {
        float* slab = hsm + kg * (32 * 132);
        const int r0 = mg * 16 + (lane >> 2);
        #pragma unroll
        for (int j = 0; j < 4; j++) {
            #pragma unroll
            for (int h2 = 0; h2 < 2; h2++) {
                int jj = 2 * j + h2;
                int col = ng * 64 + j * 16 + h2 * 8 + 2 * (lane & 3);
                float d0 = Da[jj][0] + Db[jj][0];
                float d1 = Da[jj][1] + Db[jj][1];
                float d2 = Da[jj][2] + Db[jj][2];
                float d3 = Da[jj][3] + Db[jj][3];
                *(float2*)&slab[r0 * 132 + col]       = make_float2(d0, d1);
                *(float2*)&slab[(r0 + 8) * 132 + col] = make_float2(d2, d3);
            }
        }
    }
    __syncthreads();

    // ---- epilogue: 16 warps x 2 tasks; reduce 4 kg slabs inline ----
    const int n0 = lane * 4;
    const float4 bj = *(const float4*)&b1[n0];
    const float4 w3 = *(const float4*)&W3[n0];
    const float4 w4 = *(const float4*)&W4[n0];
    const float4 w5 = *(const float4*)&W5[n0];
    const float4 w6 = *(const float4*)&W6[n0];
    const float B3 = b3[0], B4 = b4[0], B5 = b5[0], B6 = b6[0];

    #pragma unroll
    for (int it = 0; it < 2; it++) {
        int m = wid * 2 + it;
        int task = mbase + m;
        bool ok = (task < T);
        int rt = ok ? task : (T - 1);

        float4 s = *(const float4*)&hsm[m * 132 + n0];
        #pragma unroll
        for (int q = 1; q < 4; q++) {
            float4 p2 = *(const float4*)&hsm[q * (32 * 132) + m * 132 + n0];
            s.x += p2.x; s.y += p2.y; s.z += p2.z; s.w += p2.w;
        }
        float h0 = fmaxf(s.x + bj.x, 0.f), h1 = fmaxf(s.y + bj.y, 0.f);
        float h2 = fmaxf(s.z + bj.z, 0.f), h3 = fmaxf(s.w + bj.w, 0.f);
        float p3 = h0*w3.x + h1*w3.y + h2*w3.z + h3*w3.w;
        float p4 = h0*w4.x + h1*w4.y + h2*w4.z + h3*w4.w;
        float p5 = h0*w5.x + h1*w5.y + h2*w5.z + h3*w5.w;
        float p6 = h0*w6.x + h1*w6.y + h2*w6.z + h3*w6.w;

        float se = enode[(size_t)rt * 64 + lane] + enode[(size_t)rt * 64 + lane + 32];
        float sc = (lane < 4) ? ccl[rt * 4 + lane] : 0.0f;
        float sn = cnd[(size_t)rt * 32 + lane];

        #pragma unroll
        for (int off = 16; off; off >>= 1) {
            p3 += __shfl_xor_sync(0xffffffffu, p3, off);
            p4 += __shfl_xor_sync(0xffffffffu, p4, off);
            p5 += __shfl_xor_sync(0xffffffffu, p5, off);
            p6 += __shfl_xor_sync(0xffffffffu, p6, off);
            se += __shfl_xor_sync(0xffffffffu, se, off);
            sc += __shfl_xor_sync(0xffffffffu, sc, off);
            sn += __shfl_xor_sync(0xffffffffu, sn, off);
        }
        if (lane == 0 && ok) {
            float me = se * (1.0f / 64.0f);
            float ss = sc * sn;
            float y51 = 1.0f / (1.0f + expf(-(p3 * me + B3)));
            float y61 = p4 * me + B4;
            float y52 = 1.0f / (1.0f + expf(-(p5 * ss + B5)));
            float y62 = p6 * ss + B6;
            float p2 = y51 * y52;
            out[task] = (1.0f - p2) * (-100.0f) + p2 * (y61 + y62);
        }
    }
}

// -----------------------------------------------------------------------------
extern "C" void kernel_launch(void* const* d_in, const int* in_sizes, int n_in,
                              void* d_out, int out_size) {
    const float* bb    = (const float*)d_in[2];
    const float* res   = (const float*)d_in[3];
    const float* fr    = (const float*)d_in[4];
    const float* estep = (const float*)d_in[5];
    const float* enode = (const float*)d_in[6];
    const float* ccl   = (const float*)d_in[7];
    const float* cnd   = (const float*)d_in[8];
    const float* W1    = (const float*)d_in[9];
    const float* b1    = (const float*)d_in[10];
    const float* W3    = (const float*)d_in[11];
    const float* b3    = (const float*)d_in[12];
    const float* W4    = (const float*)d_in[13];
    const float* b4    = (const float*)d_in[14];
    const float* W5    = (const float*)d_in[15];
    const float* b5    = (const float*)d_in[16];
    const float* W6    = (const float*)d_in[17];
    const float* b6    = (const float*)d_in[18];

    int T = in_sizes[2] / D_BB;

    static int cfg = 0;
    if (!cfg) {
        cudaFuncSetAttribute(critic_mma,
                             cudaFuncAttributeMaxDynamicSharedMemorySize,
                             SMEM_TOTAL);
        cfg = 1;
    }

    prep_B<<<120, 256>>>(W1);
    critic_mma<<<(T + 31) / 32, 512, SMEM_TOTAL>>>(
        bb, res, fr, estep, enode, ccl, cnd,
        b1, W3, b3, W4, b4, W5, b5, W6, b6, (float*)d_out, T);
}

// round 13
// speedup vs baseline: 1.8374x; 1.0879x over previous
#include <cuda_runtime.h>
#include <cuda_fp16.h>
#include <math.h>
#include <stdint.h>

#define D_BB 768
#define KPAD 960          // 160 feat(+pad) + 768 bb + 32 pad
#define CH   64           // k per sub-chunk
#define NCH  15           // sub-chunks
#define NPAIR 8           // chunk pairs (last pair = chunk 14 only)
#define SUBB 20480        // per sub-stage: A 4K | B 16K
#define SMEM_TOTAL (6 * SUBB)   // 3 pair-stages x 2 sub-stages = 122880

typedef unsigned long long u64;
typedef unsigned int       u32;

// ---- W1 as fp16, transposed [n][k], remapped/padded -------------------------
__device__ __align__(16) __half g_B[128 * KPAD];

// ---- helpers -----------------------------------------------------------------
__device__ __forceinline__ u32 smem_u32(const void* p) {
    u32 a;
    asm("{ .reg .u64 t; cvta.to.shared.u64 t, %1; cvt.u32.u64 %0, t; }"
        : "=r"(a) : "l"(p));
    return a;
}
__device__ __forceinline__ u32 SWZ(u32 b) { return b ^ ((b >> 3) & 0x70); }

__device__ __forceinline__ u32 pack_h2(float lo, float hi) {
    __half2 v = __floats2half2_rn(lo, hi);
    return *(u32*)&v;
}

#define LDMX4(r, addr) \
    asm volatile("ldmatrix.sync.aligned.m8n8.x4.shared.b16 {%0,%1,%2,%3}, [%4];" \
        : "=r"((r)[0]), "=r"((r)[1]), "=r"((r)[2]), "=r"((r)[3]) : "r"(addr))

#define MMAF16(d, a, b0, b1) \
    asm volatile("mma.sync.aligned.m16n8k16.row.col.f32.f16.f16.f32 " \
        "{%0,%1,%2,%3}, {%4,%5,%6,%7}, {%8,%9}, {%0,%1,%2,%3};" \
        : "+f"((d)[0]), "+f"((d)[1]), "+f"((d)[2]), "+f"((d)[3]) \
        : "r"((a)[0]), "r"((a)[1]), "r"((a)[2]), "r"((a)[3]), "r"(b0), "r"(b1))

#define CPA16(dst, src) \
    asm volatile("cp.async.cg.shared.global [%0], [%1], 16;" \
        :: "r"(dst), "l"(src) : "memory")
#define CPA_COMMIT() asm volatile("cp.async.commit_group;" ::: "memory")
#define CPA_WAIT(n)  asm volatile("cp.async.wait_group %0;" :: "n"(n) : "memory")

#define STS64(r0, r1, sa) \
    asm volatile("st.shared.v2.b32 [%0], {%1, %2};" \
        :: "r"(sa), "r"(r0), "r"(r1) : "memory")

// -----------------------------------------------------------------------------
// Prep: W1 [918,128] fp32 -> g_B [128 n][960 k] fp16 (row remap + zero pad).
// -----------------------------------------------------------------------------
__global__ void prep_B(const float* __restrict__ W1) {
    int id = blockIdx.x * 256 + threadIdx.x;        // 128 n * 240 groups of 4
    if (id >= 128 * 240) return;
    int n  = id / 240;
    int k4 = (id % 240) * 4;
    u32 w[2];
    #pragma unroll
    for (int p = 0; p < 2; p++) {
        float v0 = 0.f, v1 = 0.f;
        int g0 = k4 + p * 2, g1 = g0 + 1;
        if (g0 < 150)                    v0 = W1[(size_t)g0 * 128 + n];
        else if (g0 >= 160 && g0 < 928)  v0 = W1[(size_t)(g0 - 10) * 128 + n];
        if (g1 < 150)                    v1 = W1[(size_t)g1 * 128 + n];
        else if (g1 >= 160 && g1 < 928)  v1 = W1[(size_t)(g1 - 10) * 128 + n];
        w[p] = pack_h2(v0, v1);
    }
    *(u64*)&g_B[(size_t)n * KPAD + k4] = (u64)w[0] | ((u64)w[1] << 32);
}

// -----------------------------------------------------------------------------
// Fused kernel: grid = T/32 CTAs, 512 threads.
// 16 warps = 2M x 2N x 4K-groups; warp tile 16 rows x 64 cols.
// Paired-chunk pipeline: 3 pair-stages, ONE sync per 2 chunks.
// Single-pass fp16 (A fp16, B fp16, fp32 accumulate).
// -----------------------------------------------------------------------------
__global__ void __launch_bounds__(512)
critic_mma(const float* __restrict__ bb,
           const float* __restrict__ res,   const float* __restrict__ fr,
           const float* __restrict__ estep, const float* __restrict__ enode,
           const float* __restrict__ ccl,   const float* __restrict__ cnd,
           const float* __restrict__ b1,
           const float* __restrict__ W3, const float* __restrict__ b3,
           const float* __restrict__ W4, const float* __restrict__ b4,
           const float* __restrict__ W5, const float* __restrict__ b5,
           const float* __restrict__ W6, const float* __restrict__ b6,
           float* __restrict__ out, int T)
{
    extern __shared__ __align__(16) char dsm[];
    const u32 sb = smem_u32(dsm);

    const int tid  = threadIdx.x;
    const int lane = tid & 31;
    const int wid  = tid >> 5;
    const int mbase = blockIdx.x * 32;

    const int kg = wid & 3;
    const int mg = (wid >> 2) & 1;
    const int ng = wid >> 3;

    // sub-stage base for chunk c: pair (c>>1)%3, half c&1
    auto stageBase = [&](int c) -> u32 {
        return sb + (u32)((((c >> 1) % 3) * 2 + (c & 1)) * SUBB);
    };

    // ---- A loader mapping: thread -> (row, 4 consecutive k) ----
    const int ar = tid >> 4;
    const int ak = (tid & 15) * 4;
    int atask = mbase + ar; if (atask >= T) atask = T - 1;
    const float* bbrow = bb + (size_t)atask * D_BB;
    const u32 aoff = SWZ((u32)(ar * 128 + ak * 2));

    // ---- B loader mapping: 2 x (row, 16B seg) per thread ----
    int brow[2], bseg[2]; u32 bdst[2];
    #pragma unroll
    for (int i = 0; i < 2; i++) {
        int id = tid + i * 512;
        brow[i] = id >> 3;
        bseg[i] = id & 7;
        bdst[i] = SWZ((u32)(brow[i] * 128 + bseg[i] * 16));
    }

    // ---- fragment offsets (within sub-stage) ----
    const u32 aOff = SWZ((u32)((mg * 16 + (lane & 7) + ((lane >> 3) & 1) * 8) * 128
                               + (lane >> 4) * 16 + kg * 32));
    u32 bOff[4];
    #pragma unroll
    for (int j = 0; j < 4; j++)
        bOff[j] = SWZ((u32)((ng * 64 + j * 16 + (lane >> 4) * 8 + (lane & 7)) * 128
                            + ((lane >> 3) & 1) * 16 + kg * 32));

    float Da[8][4];
    #pragma unroll
    for (int j = 0; j < 8; j++)
        #pragma unroll
        for (int q = 0; q < 4; q++) Da[j][q] = 0.f;

    auto loadA_gen = [&](int c, float* x) {
        int g0 = c * CH + ak;
        if (g0 >= 160 && g0 + 4 <= 928) {
            float4 v = *(const float4*)(bbrow + (g0 - 160));
            x[0] = v.x; x[1] = v.y; x[2] = v.z; x[3] = v.w;
        } else {
            #pragma unroll
            for (int j = 0; j < 4; j++) {
                int gk = g0 + j;
                float v = 0.f;
                if (gk < 150) {
                    int nn = gk / 30, rem = gk - nn * 30;
                    int mm = rem / 6, oo = rem - mm * 6;
                    v = res[atask * 5 + nn] * fr[atask * 5 + mm] * estep[atask * 6 + oo];
                } else if (gk >= 160 && gk < 928) {
                    v = bbrow[gk - 160];
                }
                x[j] = v;
            }
        }
    };
    auto loadA_bb = [&](int c, float* x) {
        int g0 = c * CH + ak;
        if (g0 + 4 <= 928) {
            float4 v = *(const float4*)(bbrow + (g0 - 160));
            x[0] = v.x; x[1] = v.y; x[2] = v.z; x[3] = v.w;
        } else {
            x[0] = x[1] = x[2] = x[3] = 0.f;
        }
    };
    auto storeA = [&](int c, const float* x) {
        const u32 base = stageBase(c);
        STS64(pack_h2(x[0], x[1]), pack_h2(x[2], x[3]), base + aoff);
    };
    auto issueB = [&](int c) {
        const u32 base = stageBase(c);
        #pragma unroll
        for (int i = 0; i < 2; i++) {
            const size_t so = (size_t)brow[i] * KPAD + c * CH + bseg[i] * 8;
            CPA16(base + 4096 + bdst[i], g_B + so);
        }
    };
    auto compute = [&](int c) {
        const u32 base = stageBase(c);
        u32 ah[4], bf[4][4];
        LDMX4(ah, base + aOff);
        #pragma unroll
        for (int j = 0; j < 4; j++) LDMX4(bf[j], base + 4096 + bOff[j]);
        #pragma unroll
        for (int j = 0; j < 4; j++) {
            MMAF16(Da[2*j],   ah, bf[j][0], bf[j][1]);
            MMAF16(Da[2*j+1], ah, bf[j][2], bf[j][3]);
        }
    };

    // ---- prologue: pairs 0,1 staged; A for pair 2 prefetched ----
    float xa[4], xb[4];
    loadA_gen(0, xa); loadA_gen(1, xb);
    storeA(0, xa); storeA(1, xb); issueB(0); issueB(1); CPA_COMMIT();
    loadA_gen(2, xa); loadA_gen(3, xb);
    storeA(2, xa); storeA(3, xb); issueB(2); issueB(3); CPA_COMMIT();
    loadA_bb(4, xa); loadA_bb(5, xb);
    CPA_WAIT(1);             // pair 0 arrived
    __syncthreads();

    // ---- main loop: one sync per pair ----
    for (int p = 0; p < NPAIR; p++) {
        const int c0 = 2 * p;
        compute(c0);
        if (c0 + 1 < NCH) compute(c0 + 1);

        if (p + 2 < NPAIR) {
            const int cA = c0 + 4, cB = c0 + 5;
            storeA(cA, xa);
            if (cB < NCH) storeA(cB, xb);
            if (p + 3 < NPAIR) {
                loadA_bb(cA + 2, xa);
                if (cB + 2 < NCH) loadA_bb(cB + 2, xb);
            }
            issueB(cA);
            if (cB < NCH) issueB(cB);
            CPA_COMMIT();
            CPA_WAIT(1);     // pair p+1 arrived
        } else if (p + 1 < NPAIR) {
            CPA_WAIT(0);     // final pair arrived
        }
        __syncthreads();
    }

    // ---- write kg-partial D to smem: hsm[4][32][132] ----
    float* hsm = (float*)dsm;
    {
        float* slab = hsm + kg * (32 * 132);
        const int r0 = mg * 16 + (lane >> 2);
        #pragma unroll
        for (int j = 0; j < 4; j++) {
            #pragma unroll
            for (int h2 = 0; h2 < 2; h2++) {
                int jj = 2 * j + h2;
                int col = ng * 64 + j * 16 + h2 * 8 + 2 * (lane & 3);
                *(float2*)&slab[r0 * 132 + col]       = make_float2(Da[jj][0], Da[jj][1]);
                *(float2*)&slab[(r0 + 8) * 132 + col] = make_float2(Da[jj][2], Da[jj][3]);
            }
        }
    }
    __syncthreads();

    // ---- epilogue: 16 warps x 2 tasks; reduce 4 kg slabs inline ----
    const int n0 = lane * 4;
    const float4 bj = *(const float4*)&b1[n0];
    const float4 w3 = *(const float4*)&W3[n0];
    const float4 w4 = *(const float4*)&W4[n0];
    const float4 w5 = *(const float4*)&W5[n0];
    const float4 w6 = *(const float4*)&W6[n0];
    const float B3 = b3[0], B4 = b4[0], B5 = b5[0], B6 = b6[0];

    #pragma unroll
    for (int it = 0; it < 2; it++) {
        int m = wid * 2 + it;
        int task = mbase + m;
        bool ok = (task < T);
        int rt = ok ? task : (T - 1);

        float4 s = *(const float4*)&hsm[m * 132 + n0];
        #pragma unroll
        for (int q = 1; q < 4; q++) {
            float4 p2 = *(const float4*)&hsm[q * (32 * 132) + m * 132 + n0];
            s.x += p2.x; s.y += p2.y; s.z += p2.z; s.w += p2.w;
        }
        float h0 = fmaxf(s.x + bj.x, 0.f), h1 = fmaxf(s.y + bj.y, 0.f);
        float h2 = fmaxf(s.z + bj.z, 0.f), h3 = fmaxf(s.w + bj.w, 0.f);
        float p3 = h0*w3.x + h1*w3.y + h2*w3.z + h3*w3.w;
        float p4 = h0*w4.x + h1*w4.y + h2*w4.z + h3*w4.w;
        float p5 = h0*w5.x + h1*w5.y + h2*w5.z + h3*w5.w;
        float p6 = h0*w6.x + h1*w6.y + h2*w6.z + h3*w6.w;

        float se = enode[(size_t)rt * 64 + lane] + enode[(size_t)rt * 64 + lane + 32];
        float sc = (lane < 4) ? ccl[rt * 4 + lane] : 0.0f;
        float sn = cnd[(size_t)rt * 32 + lane];

        #pragma unroll
        for (int off = 16; off; off >>= 1) {
            p3 += __shfl_xor_sync(0xffffffffu, p3, off);
            p4 += __shfl_xor_sync(0xffffffffu, p4, off);
            p5 += __shfl_xor_sync(0xffffffffu, p5, off);
            p6 += __shfl_xor_sync(0xffffffffu, p6, off);
            se += __shfl_xor_sync(0xffffffffu, se, off);
            sc += __shfl_xor_sync(0xffffffffu, sc, off);
            sn += __shfl_xor_sync(0xffffffffu, sn, off);
        }
        if (lane == 0 && ok) {
            float me = se * (1.0f / 64.0f);
            float ss = sc * sn;
            float y51 = 1.0f / (1.0f + expf(-(p3 * me + B3)));
            float y61 = p4 * me + B4;
            float y52 = 1.0f / (1.0f + expf(-(p5 * ss + B5)));
            float y62 = p6 * ss + B6;
            float p2 = y51 * y52;
            out[task] = (1.0f - p2) * (-100.0f) + p2 * (y61 + y62);
        }
    }
}

// -----------------------------------------------------------------------------
extern "C" void kernel_launch(void* const* d_in, const int* in_sizes, int n_in,
                              void* d_out, int out_size) {
    const float* bb    = (const float*)d_in[2];
    const float* res   = (const float*)d_in[3];
    const float* fr    = (const float*)d_in[4];
    const float* estep = (const float*)d_in[5];
    const float* enode = (const float*)d_in[6];
    const float* ccl   = (const float*)d_in[7];
    const float* cnd   = (const float*)d_in[8];
    const float* W1    = (const float*)d_in[9];
    const float* b1    = (const float*)d_in[10];
    const float* W3    = (const float*)d_in[11];
    const float* b3    = (const float*)d_in[12];
    const float* W4    = (const float*)d_in[13];
    const float* b4    = (const float*)d_in[14];
    const float* W5    = (const float*)d_in[15];
    const float* b5    = (const float*)d_in[16];
    const float* W6    = (const float*)d_in[17];
    const float* b6    = (const float*)d_in[18];

    int T = in_sizes[2] / D_BB;

    static int cfg = 0;
    if (!cfg) {
        cudaFuncSetAttribute(critic_mma,
                             cudaFuncAttributeMaxDynamicSharedMemorySize,
                             SMEM_TOTAL);
        cfg = 1;
    }

    prep_B<<<120, 256>>>(W1);
    critic_mma<<<(T + 31) / 32, 512, SMEM_TOTAL>>>(
        bb, res, fr, estep, enode, ccl, cnd,
        b1, W3, b3, W4, b4, W5, b5, W6, b6, (float*)d_out, T);
}

// round 14
// speedup vs baseline: 1.8617x; 1.0133x over previous
#include <cuda_runtime.h>
#include <cuda_fp16.h>
#include <math.h>
#include <stdint.h>

#define D_BB 768
#define CH   64           // k per sub-chunk
#define NCH  15           // sub-chunks
#define NPAIR 8           // chunk pairs (last pair = chunk 14 only)
#define SUBB 20480        // per sub-stage: A 4K | B 16K
#define SMEM_TOTAL (6 * SUBB)   // 3 pair-stages x 2 sub-stages = 122880

typedef unsigned long long u64;
typedef unsigned int       u32;

// ---- helpers -----------------------------------------------------------------
__device__ __forceinline__ u32 smem_u32(const void* p) {
    u32 a;
    asm("{ .reg .u64 t; cvta.to.shared.u64 t, %1; cvt.u32.u64 %0, t; }"
        : "=r"(a) : "l"(p));
    return a;
}
__device__ __forceinline__ u32 SWZ(u32 b) { return b ^ ((b >> 3) & 0x70); }

__device__ __forceinline__ u32 pack_h2(float lo, float hi) {
    __half2 v = __floats2half2_rn(lo, hi);
    return *(u32*)&v;
}

#define LDMX4(r, addr) \
    asm volatile("ldmatrix.sync.aligned.m8n8.x4.shared.b16 {%0,%1,%2,%3}, [%4];" \
        : "=r"((r)[0]), "=r"((r)[1]), "=r"((r)[2]), "=r"((r)[3]) : "r"(addr))

#define MMAF16(d, a, b0, b1) \
    asm volatile("mma.sync.aligned.m16n8k16.row.col.f32.f16.f16.f32 " \
        "{%0,%1,%2,%3}, {%4,%5,%6,%7}, {%8,%9}, {%0,%1,%2,%3};" \
        : "+f"((d)[0]), "+f"((d)[1]), "+f"((d)[2]), "+f"((d)[3]) \
        : "r"((a)[0]), "r"((a)[1]), "r"((a)[2]), "r"((a)[3]), "r"(b0), "r"(b1))

#define STS64(r0, r1, sa) \
    asm volatile("st.shared.v2.b32 [%0], {%1, %2};" \
        :: "r"(sa), "r"(r0), "r"(r1) : "memory")

// -----------------------------------------------------------------------------
// Single fused kernel: grid = T/32 CTAs, 512 threads.
// 16 warps = 2M x 2N x 4K-groups; warp tile 16 rows x 64 cols.
// Paired-chunk pipeline: 3 pair-stages, ONE sync per 2 chunks.
// Single-pass fp16; B converted in-CTA from fp32 W1 (no prep kernel).
// -----------------------------------------------------------------------------
__global__ void __launch_bounds__(512)
critic_mma(const float* __restrict__ bb,
           const float* __restrict__ res,   const float* __restrict__ fr,
           const float* __restrict__ estep, const float* __restrict__ enode,
           const float* __restrict__ ccl,   const float* __restrict__ cnd,
           const float* __restrict__ W1,    const float* __restrict__ b1,
           const float* __restrict__ W3, const float* __restrict__ b3,
           const float* __restrict__ W4, const float* __restrict__ b4,
           const float* __restrict__ W5, const float* __restrict__ b5,
           const float* __restrict__ W6, const float* __restrict__ b6,
           float* __restrict__ out, int T)
{
    extern __shared__ __align__(16) char dsm[];
    const u32 sb = smem_u32(dsm);

    const int tid  = threadIdx.x;
    const int lane = tid & 31;
    const int wid  = tid >> 5;
    const int mbase = blockIdx.x * 32;

    const int kg = wid & 3;
    const int mg = (wid >> 2) & 1;
    const int ng = wid >> 3;

    // sub-stage base for chunk c: pair (c>>1)%3, half c&1
    auto stageBase = [&](int c) -> u32 {
        return sb + (u32)((((c >> 1) % 3) * 2 + (c & 1)) * SUBB);
    };

    // ---- A loader mapping: thread -> (row, 4 consecutive k) ----
    const int ar = tid >> 4;
    const int ak = (tid & 15) * 4;
    int atask = mbase + ar; if (atask >= T) atask = T - 1;
    const float* bbrow = bb + (size_t)atask * D_BB;
    const u32 aoff = SWZ((u32)(ar * 128 + ak * 2));

    // ---- B conversion loader: thread -> (n row, 16 consecutive k) ----
    const int bn  = tid & 127;          // n (smem row / W1 column)
    const int bkg = tid >> 7;           // 0..3, k sub-group (warp-uniform)
    u32 boffs[4];
    #pragma unroll
    for (int g = 0; g < 4; g++)
        boffs[g] = SWZ((u32)(bn * 128 + bkg * 32 + g * 8));

    // ---- fragment offsets (within sub-stage) ----
    const u32 aOff = SWZ((u32)((mg * 16 + (lane & 7) + ((lane >> 3) & 1) * 8) * 128
                               + (lane >> 4) * 16 + kg * 32));
    u32 bOff[4];
    #pragma unroll
    for (int j = 0; j < 4; j++)
        bOff[j] = SWZ((u32)((ng * 64 + j * 16 + (lane >> 4) * 8 + (lane & 7)) * 128
                            + ((lane >> 3) & 1) * 16 + kg * 32));

    float Da[8][4];
    #pragma unroll
    for (int j = 0; j < 8; j++)
        #pragma unroll
        for (int q = 0; q < 4; q++) Da[j][q] = 0.f;

    auto loadA_gen = [&](int c, float* x) {
        int g0 = c * CH + ak;
        if (g0 >= 160 && g0 + 4 <= 928) {
            float4 v = *(const float4*)(bbrow + (g0 - 160));
            x[0] = v.x; x[1] = v.y; x[2] = v.z; x[3] = v.w;
        } else {
            #pragma unroll
            for (int j = 0; j < 4; j++) {
                int gk = g0 + j;
                float v = 0.f;
                if (gk < 150) {
                    int nn = gk / 30, rem = gk - nn * 30;
                    int mm = rem / 6, oo = rem - mm * 6;
                    v = res[atask * 5 + nn] * fr[atask * 5 + mm] * estep[atask * 6 + oo];
                } else if (gk >= 160 && gk < 928) {
                    v = bbrow[gk - 160];
                }
                x[j] = v;
            }
        }
    };
    auto loadA_bb = [&](int c, float* x) {
        int g0 = c * CH + ak;
        if (g0 + 4 <= 928) {
            float4 v = *(const float4*)(bbrow + (g0 - 160));
            x[0] = v.x; x[1] = v.y; x[2] = v.z; x[3] = v.w;
        } else {
            x[0] = x[1] = x[2] = x[3] = 0.f;
        }
    };
    auto storeA = [&](int c, const float* x) {
        const u32 base = stageBase(c);
        STS64(pack_h2(x[0], x[1]), pack_h2(x[2], x[3]), base + aoff);
    };

    // B: gather 16 fp32 from W1 (row remap 918->960, warp-uniform predicates)
    auto loadB = [&](int c, float* y) {
        int k0 = c * CH + bkg * 16;
        #pragma unroll
        for (int j = 0; j < 16; j++) {
            int gk = k0 + j;
            int sr = (gk < 160) ? gk : gk - 10;
            float v = 0.f;
            if (gk < 150 || (gk >= 160 && gk < 928))
                v = W1[(size_t)sr * 128 + bn];
            y[j] = v;
        }
    };
    auto storeB = [&](int c, const float* y) {
        const u32 base = stageBase(c) + 4096;
        #pragma unroll
        for (int g = 0; g < 4; g++)
            STS64(pack_h2(y[4*g], y[4*g+1]), pack_h2(y[4*g+2], y[4*g+3]),
                  base + boffs[g]);
    };

    auto compute = [&](int c) {
        const u32 base = stageBase(c);
        u32 ah[4], bf[4][4];
        LDMX4(ah, base + aOff);
        #pragma unroll
        for (int j = 0; j < 4; j++) LDMX4(bf[j], base + 4096 + bOff[j]);
        #pragma unroll
        for (int j = 0; j < 4; j++) {
            MMAF16(Da[2*j],   ah, bf[j][0], bf[j][1]);
            MMAF16(Da[2*j+1], ah, bf[j][2], bf[j][3]);
        }
    };

    // ---- prologue: pairs 0,1 staged; pair 2 prefetched to regs ----
    float xa[4], xb[4], ya[16], yb[16];
    loadA_gen(0, xa); loadB(0, ya);
    loadA_gen(1, xb); loadB(1, yb);
    storeA(0, xa); storeB(0, ya);
    storeA(1, xb); storeB(1, yb);
    loadA_gen(2, xa); loadB(2, ya);
    loadA_gen(3, xb); loadB(3, yb);
    storeA(2, xa); storeB(2, ya);
    storeA(3, xb); storeB(3, yb);
    loadA_bb(4, xa); loadB(4, ya);
    loadA_bb(5, xb); loadB(5, yb);
    __syncthreads();

    // ---- main loop: one sync per pair ----
    for (int p = 0; p < NPAIR; p++) {
        const int c0 = 2 * p;
        compute(c0);
        if (c0 + 1 < NCH) compute(c0 + 1);

        if (p + 2 < NPAIR) {
            const int cA = c0 + 4, cB = c0 + 5;
            storeA(cA, xa); storeB(cA, ya);
            if (cB < NCH) { storeA(cB, xb); storeB(cB, yb); }
            if (p + 3 < NPAIR) {
                loadA_bb(cA + 2, xa); loadB(cA + 2, ya);
                if (cB + 2 < NCH) { loadA_bb(cB + 2, xb); loadB(cB + 2, yb); }
            }
        }
        __syncthreads();
    }

    // ---- write kg-partial D to smem: hsm[4][32][132] ----
    float* hsm = (float*)dsm;
    {
        float* slab = hsm + kg * (32 * 132);
        const int r0 = mg * 16 + (lane >> 2);
        #pragma unroll
        for (int j = 0; j < 4; j++) {
            #pragma unroll
            for (int h2 = 0; h2 < 2; h2++) {
                int jj = 2 * j + h2;
                int col = ng * 64 + j * 16 + h2 * 8 + 2 * (lane & 3);
                *(float2*)&slab[r0 * 132 + col]       = make_float2(Da[jj][0], Da[jj][1]);
                *(float2*)&slab[(r0 + 8) * 132 + col] = make_float2(Da[jj][2], Da[jj][3]);
            }
        }
    }
    __syncthreads();

    // ---- epilogue: 16 warps x 2 tasks; reduce 4 kg slabs inline ----
    const int n0 = lane * 4;
    const float4 bj = *(const float4*)&b1[n0];
    const float4 w3 = *(const float4*)&W3[n0];
    const float4 w4 = *(const float4*)&W4[n0];
    const float4 w5 = *(const float4*)&W5[n0];
    const float4 w6 = *(const float4*)&W6[n0];
    const float B3 = b3[0], B4 = b4[0], B5 = b5[0], B6 = b6[0];

    #pragma unroll
    for (int it = 0; it < 2; it++) {
        int m = wid * 2 + it;
        int task = mbase + m;
        bool ok = (task < T);
        int rt = ok ? task : (T - 1);

        float4 s = *(const float4*)&hsm[m * 132 + n0];
        #pragma unroll
        for (int q = 1; q < 4; q++) {
            float4 p2 = *(const float4*)&hsm[q * (32 * 132) + m * 132 + n0];
            s.x += p2.x; s.y += p2.y; s.z += p2.z; s.w += p2.w;
        }
        float h0 = fmaxf(s.x + bj.x, 0.f), h1 = fmaxf(s.y + bj.y, 0.f);
        float h2 = fmaxf(s.z + bj.z, 0.f), h3 = fmaxf(s.w + bj.w, 0.f);
        float p3 = h0*w3.x + h1*w3.y + h2*w3.z + h3*w3.w;
        float p4 = h0*w4.x + h1*w4.y + h2*w4.z + h3*w4.w;
        float p5 = h0*w5.x + h1*w5.y + h2*w5.z + h3*w5.w;
        float p6 = h0*w6.x + h1*w6.y + h2*w6.z + h3*w6.w;

        float se = enode[(size_t)rt * 64 + lane] + enode[(size_t)rt * 64 + lane + 32];
        float sc = (lane < 4) ? ccl[rt * 4 + lane] : 0.0f;
        float sn = cnd[(size_t)rt * 32 + lane];

        #pragma unroll
        for (int off = 16; off; off >>= 1) {
            p3 += __shfl_xor_sync(0xffffffffu, p3, off);
            p4 += __shfl_xor_sync(0xffffffffu, p4, off);
            p5 += __shfl_xor_sync(0xffffffffu, p5, off);
            p6 += __shfl_xor_sync(0xffffffffu, p6, off);
            se += __shfl_xor_sync(0xffffffffu, se, off);
            sc += __shfl_xor_sync(0xffffffffu, sc, off);
            sn += __shfl_xor_sync(0xffffffffu, sn, off);
        }
        if (lane == 0 && ok) {
            float me = se * (1.0f / 64.0f);
            float ss = sc * sn;
            float y51 = 1.0f / (1.0f + expf(-(p3 * me + B3)));
            float y61 = p4 * me + B4;
            float y52 = 1.0f / (1.0f + expf(-(p5 * ss + B5)));
            float y62 = p6 * ss + B6;
            float p2 = y51 * y52;
            out[task] = (1.0f - p2) * (-100.0f) + p2 * (y61 + y62);
        }
    }
}

// -----------------------------------------------------------------------------
extern "C" void kernel_launch(void* const* d_in, const int* in_sizes, int n_in,
                              void* d_out, int out_size) {
    const float* bb    = (const float*)d_in[2];
    const float* res   = (const float*)d_in[3];
    const float* fr    = (const float*)d_in[4];
    const float* estep = (const float*)d_in[5];
    const float* enode = (const float*)d_in[6];
    const float* ccl   = (const float*)d_in[7];
    const float* cnd   = (const float*)d_in[8];
    const float* W1    = (const float*)d_in[9];
    const float* b1    = (const float*)d_in[10];
    const float* W3    = (const float*)d_in[11];
    const float* b3    = (const float*)d_in[12];
    const float* W4    = (const float*)d_in[13];
    const float* b4    = (const float*)d_in[14];
    const float* W5    = (const float*)d_in[15];
    const float* b5    = (const float*)d_in[16];
    const float* W6    = (const float*)d_in[17];
    const float* b6    = (const float*)d_in[18];

    int T = in_sizes[2] / D_BB;

    static int cfg = 0;
    if (!cfg) {
        cudaFuncSetAttribute(critic_mma,
                             cudaFuncAttributeMaxDynamicSharedMemorySize,
                             SMEM_TOTAL);
        cfg = 1;
    }

    critic_mma<<<(T + 31) / 32, 512, SMEM_TOTAL>>>(
        bb, res, fr, estep, enode, ccl, cnd, W1,
        b1, W3, b3, W4, b4, W5, b5, W6, b6, (float*)d_out, T);
}